// round 2
// baseline (speedup 1.0000x reference)
#include <cuda_runtime.h>

#define NN 100000
#define NE 1600000
#define DIN 128
#define DH  64

// Scratch (static device globals — no allocation allowed)
__device__ __align__(16) float g_y[NN * DH];     // x @ w1a
__device__ __align__(16) float g_z[NN * DH];     // h1 @ w2a
__device__ __align__(16) float g_agg1[NN * DH];  // segment_sum of y
__device__ __align__(16) float g_agg2[NN * DH];  // segment_sum of z
__device__ __align__(16) float g_sums[DH];       // global pooled sum of relu(...)

// ---------------------------------------------------------------------------
// Zero the scatter targets + pooled sums
// ---------------------------------------------------------------------------
__global__ void zero_kernel() {
    int i = blockIdx.x * blockDim.x + threadIdx.x;
    const int n4 = NN * DH / 4;  // 1.6M float4 per array
    if (i < n4) {
        ((float4*)g_agg1)[i] = make_float4(0.f, 0.f, 0.f, 0.f);
        ((float4*)g_agg2)[i] = make_float4(0.f, 0.f, 0.f, 0.f);
    }
    if (i < DH) g_sums[i] = 0.f;
}

// ---------------------------------------------------------------------------
// GEMM1: y = x @ w1a      [100000,128] x [128,64]
// 64 nodes per block, 256 threads, each thread computes 4 nodes x 4 outputs.
// ---------------------------------------------------------------------------
__global__ void gemm1_kernel(const float* __restrict__ x,
                             const float* __restrict__ w1a) {
    extern __shared__ float sm[];
    float* ws = sm;                 // 128*64 = 8192 floats
    float* xs = sm + DIN * DH;      // 64 rows, stride 132 (pad: bank + 16B align)

    const int t = threadIdx.x;
    const int nb = blockIdx.x * 64;

    // load weights (row-major [k][o])
    #pragma unroll
    for (int i = 0; i < (DIN * DH) / 256; i++)
        ws[i * 256 + t] = w1a[i * 256 + t];

    // load x tile: 64 nodes x 128 feats = 2048 float4
    #pragma unroll
    for (int i = 0; i < 8; i++) {
        int flat = i * 256 + t;     // float4 index
        int node = flat >> 5;       // 32 float4 per row
        int f4   = flat & 31;
        float4 v = make_float4(0.f, 0.f, 0.f, 0.f);
        if (nb + node < NN)
            v = ((const float4*)x)[(size_t)(nb + node) * 32 + f4];
        *(float4*)&xs[node * 132 + f4 * 4] = v;
    }
    __syncthreads();

    const int ng = t >> 4;   // node group: nodes 4ng..4ng+3
    const int og = t & 15;   // out group:  outs  4og..4og+3

    float acc[4][4] = {};
    #pragma unroll 4
    for (int k = 0; k < DIN; k++) {
        float4 w4 = *(const float4*)&ws[k * DH + og * 4];
        #pragma unroll
        for (int j = 0; j < 4; j++) {
            float xv = xs[(ng * 4 + j) * 132 + k];
            acc[j][0] += xv * w4.x;
            acc[j][1] += xv * w4.y;
            acc[j][2] += xv * w4.z;
            acc[j][3] += xv * w4.w;
        }
    }
    #pragma unroll
    for (int j = 0; j < 4; j++) {
        int node = nb + ng * 4 + j;
        if (node < NN)
            ((float4*)g_y)[(size_t)node * 16 + og] =
                make_float4(acc[j][0], acc[j][1], acc[j][2], acc[j][3]);
    }
}

// ---------------------------------------------------------------------------
// Edge scatter: agg[dst] += vec[src], 64 fp32 per edge, 16 threads/edge,
// vectorized red.global.add.v4.f32 (one L2 atomic per 16B).
// edge_index is int32 (JAX default x64-disabled downcasts int64 -> int32).
// ---------------------------------------------------------------------------
__device__ __forceinline__ void scatter_body(const float* __restrict__ vec,
                                             float* __restrict__ agg,
                                             const int* __restrict__ ei) {
    long long tid = (long long)blockIdx.x * blockDim.x + threadIdx.x;
    if (tid >= (long long)NE * 16) return;
    int e = (int)(tid >> 4);
    int c = (int)(tid & 15);
    unsigned src = (unsigned)ei[e];
    unsigned dst = (unsigned)ei[NE + e];
    if (src >= NN || dst >= NN) return;   // defensive: avoid IMA on dtype surprise
    float4 v = ((const float4*)vec)[(size_t)src * 16 + c];
    float* p = agg + ((size_t)dst * 64 + c * 4);
    asm volatile("red.global.add.v4.f32 [%0], {%1,%2,%3,%4};"
                 :: "l"(p), "f"(v.x), "f"(v.y), "f"(v.z), "f"(v.w)
                 : "memory");
}

__global__ void scatter1_kernel(const int* __restrict__ ei) {
    scatter_body(g_y, g_agg1, ei);
}
__global__ void scatter2_kernel(const int* __restrict__ ei) {
    scatter_body(g_z, g_agg2, ei);
}

// ---------------------------------------------------------------------------
// Fused middle:
//   t1 = relu(y + agg1 + b1a)         (elementwise, smem)
//   h1 = relu(t1 @ w1b + b1b)         (64x64 GEMM, smem)
//   z  = h1 @ w2a                     (64x64 GEMM, -> global)
// 64 nodes / block, 256 threads.
// ---------------------------------------------------------------------------
__global__ void fused_mid_kernel(const float* __restrict__ b1a,
                                 const float* __restrict__ w1b,
                                 const float* __restrict__ b1b,
                                 const float* __restrict__ w2a) {
    extern __shared__ float sm[];
    float* ws1 = sm;                  // 64*64
    float* ws2 = sm + 4096;           // 64*64
    float* t1s = sm + 8192;           // 64 x stride 68
    float* h1s = t1s + 64 * 68;       // 64 x stride 68
    __shared__ __align__(16) float b1as[64];
    __shared__ __align__(16) float b1bs[64];

    const int t = threadIdx.x;
    const int nb = blockIdx.x * 64;

    #pragma unroll
    for (int i = 0; i < 16; i++) {
        ws1[i * 256 + t] = w1b[i * 256 + t];
        ws2[i * 256 + t] = w2a[i * 256 + t];
    }
    if (t < 64) { b1as[t] = b1a[t]; b1bs[t] = b1b[t]; }
    __syncthreads();

    // stage 1: t1 = relu(y + agg1 + b1a)
    #pragma unroll
    for (int i = 0; i < 4; i++) {
        int flat = i * 256 + t;   // float4 index in 64x16
        int node = flat >> 4;
        int f4   = flat & 15;
        float4 v = make_float4(0.f, 0.f, 0.f, 0.f);
        if (nb + node < NN) {
            size_t g = (size_t)(nb + node) * 16 + f4;
            float4 a  = ((const float4*)g_y)[g];
            float4 b  = ((const float4*)g_agg1)[g];
            float4 bb = *(const float4*)&b1as[f4 * 4];
            v.x = fmaxf(a.x + b.x + bb.x, 0.f);
            v.y = fmaxf(a.y + b.y + bb.y, 0.f);
            v.z = fmaxf(a.z + b.z + bb.z, 0.f);
            v.w = fmaxf(a.w + b.w + bb.w, 0.f);
        }
        *(float4*)&t1s[node * 68 + f4 * 4] = v;
    }
    __syncthreads();

    const int ng = t >> 4;
    const int og = t & 15;

    // stage 2: h1 = relu(t1 @ w1b + b1b)
    {
        float acc[4][4] = {};
        #pragma unroll 4
        for (int k = 0; k < DH; k++) {
            float4 w4 = *(const float4*)&ws1[k * DH + og * 4];
            #pragma unroll
            for (int j = 0; j < 4; j++) {
                float xv = t1s[(ng * 4 + j) * 68 + k];
                acc[j][0] += xv * w4.x;
                acc[j][1] += xv * w4.y;
                acc[j][2] += xv * w4.z;
                acc[j][3] += xv * w4.w;
            }
        }
        float4 bb = *(const float4*)&b1bs[og * 4];
        #pragma unroll
        for (int j = 0; j < 4; j++) {
            float4 h;
            h.x = fmaxf(acc[j][0] + bb.x, 0.f);
            h.y = fmaxf(acc[j][1] + bb.y, 0.f);
            h.z = fmaxf(acc[j][2] + bb.z, 0.f);
            h.w = fmaxf(acc[j][3] + bb.w, 0.f);
            *(float4*)&h1s[(ng * 4 + j) * 68 + og * 4] = h;
        }
    }
    __syncthreads();

    // stage 3: z = h1 @ w2a (no bias/relu here; b2a applied in reduce stage)
    {
        float acc[4][4] = {};
        #pragma unroll 4
        for (int k = 0; k < DH; k++) {
            float4 w4 = *(const float4*)&ws2[k * DH + og * 4];
            #pragma unroll
            for (int j = 0; j < 4; j++) {
                float xv = h1s[(ng * 4 + j) * 68 + k];
                acc[j][0] += xv * w4.x;
                acc[j][1] += xv * w4.y;
                acc[j][2] += xv * w4.z;
                acc[j][3] += xv * w4.w;
            }
        }
        #pragma unroll
        for (int j = 0; j < 4; j++) {
            int node = nb + ng * 4 + j;
            if (node < NN)
                ((float4*)g_z)[(size_t)node * 16 + og] =
                    make_float4(acc[j][0], acc[j][1], acc[j][2], acc[j][3]);
        }
    }
}

// ---------------------------------------------------------------------------
// Reduce: sums = sum_nodes relu(z + agg2 + b2a)
// ---------------------------------------------------------------------------
__global__ void reduce_kernel(const float* __restrict__ b2a) {
    __shared__ float sd[256];
    const int t = threadIdx.x;
    const int ch = t & 63;
    const int ns = t >> 6;   // 0..3
    const float bias = b2a[ch];
    float acc = 0.f;
    for (int node = blockIdx.x * 4 + ns; node < NN; node += gridDim.x * 4) {
        size_t g = (size_t)node * 64 + ch;
        float v = g_z[g] + g_agg2[g] + bias;
        acc += fmaxf(v, 0.f);
    }
    sd[t] = acc;
    __syncthreads();
    if (t < 64)
        atomicAdd(&g_sums[ch], sd[t] + sd[t + 64] + sd[t + 128] + sd[t + 192]);
}

// ---------------------------------------------------------------------------
// Final: out = sums @ w2b + NN * b2b    (1 x 64)
// ---------------------------------------------------------------------------
__global__ void final_kernel(const float* __restrict__ w2b,
                             const float* __restrict__ b2b,
                             float* __restrict__ out) {
    int o = threadIdx.x;
    float acc = (float)NN * b2b[o];
    #pragma unroll 8
    for (int j = 0; j < 64; j++)
        acc += g_sums[j] * w2b[j * 64 + o];
    out[o] = acc;
}

// ---------------------------------------------------------------------------
extern "C" void kernel_launch(void* const* d_in, const int* in_sizes, int n_in,
                              void* d_out, int out_size) {
    const float* x   = (const float*)d_in[0];
    const int*   ei  = (const int*)d_in[1];   // int32 (JAX x64 disabled)
    const float* w1a = (const float*)d_in[2];
    const float* b1a = (const float*)d_in[3];
    const float* w1b = (const float*)d_in[4];
    const float* b1b = (const float*)d_in[5];
    const float* w2a = (const float*)d_in[6];
    const float* b2a = (const float*)d_in[7];
    const float* w2b = (const float*)d_in[8];
    const float* b2b = (const float*)d_in[9];
    float*       out = (float*)d_out;

    (void)in_sizes; (void)n_in; (void)out_size;

    const int SMEM_G1  = (DIN * DH + 64 * 132) * 4;           // 66560 B
    const int SMEM_MID = (2 * DH * DH + 2 * 64 * 68) * 4;     // 67584 B
    cudaFuncSetAttribute(gemm1_kernel,
                         cudaFuncAttributeMaxDynamicSharedMemorySize, SMEM_G1);
    cudaFuncSetAttribute(fused_mid_kernel,
                         cudaFuncAttributeMaxDynamicSharedMemorySize, SMEM_MID);

    zero_kernel<<<(NN * DH / 4 + 255) / 256, 256>>>();
    gemm1_kernel<<<(NN + 63) / 64, 256, SMEM_G1>>>(x, w1a);
    scatter1_kernel<<<(int)(((long long)NE * 16 + 255) / 256), 256>>>(ei);
    fused_mid_kernel<<<(NN + 63) / 64, 256, SMEM_MID>>>(b1a, w1b, b1b, w2a);
    scatter2_kernel<<<(int)(((long long)NE * 16 + 255) / 256), 256>>>(ei);
    reduce_kernel<<<1184, 256>>>(b2a);
    final_kernel<<<1, 64>>>(w2b, b2b, out);
}